// round 6
// baseline (speedup 1.0000x reference)
#include <cuda_runtime.h>

// ---------------- problem constants ----------------
constexpr int   kNumNodes   = 120000;
constexpr int   kNumMovable = 100000;
constexpr int   kNumNets    = 100000;
constexpr int   kNumPins    = 400000;
constexpr int   kNbx = 256, kNby = 256;
constexpr int   kMap = kNbx * kNby;
constexpr float kBsx = 1000.0f / 256.0f;      // 3.90625 (exact in fp32)
constexpr float kBsy = 1000.0f / 256.0f;
constexpr float kInvBsx = 256.0f / 1000.0f;
constexpr float kInvBsy = 256.0f / 1000.0f;
constexpr float kEps = 1e-6f;
constexpr float kBinArea = kBsx * kBsy;
constexpr float kHNorm = 1.0f / (kBinArea * 1.5f);   // UNIT_H_CAP
constexpr float kVNorm = 1.0f / (kBinArea * 1.5f);   // UNIT_V_CAP

// fused-kernel geometry: exactly 4 blocks per SM on 148 SMs -> co-resident
constexpr int kBlocks  = 592;
constexpr int kThreads = 256;
constexpr int kTotThreads = kBlocks * kThreads;          // 151552
constexpr int kNetsPerPass = kTotThreads / 8;            // 18944
constexpr int kNetPasses  = (kNumNets + kNetsPerPass - 1) / kNetsPerPass;   // 6
constexpr int kNodeItems  = 2 * kNumMovable;             // 200000
constexpr int kNodePasses = (kNodeItems + kTotThreads - 1) / kTotThreads;   // 2

// ---------------- device scratch (no allocs allowed) ----------------
// g_scat4[m*kMap + x*256 + y] = {A', Bx', By', P}; one red.v4 per corner.
// Zero at load; scan_y phase re-zeros in place each run.
__device__ float4 g_scat4[2 * kMap];
// g_T: [U1h, U2h, U1v, U2v], each y-major [y*256+x]
__device__ float g_T[4 * kMap];
// util, y-major
__device__ float g_util[kMap];
// grid barrier state (cnt resets each use; flag increments monotonically)
__device__ unsigned g_bar_cnt[3];
__device__ unsigned g_bar_flag[3];

__device__ __forceinline__ void red4(float4* p, float a, float b, float c, float d) {
    asm volatile("red.global.add.v4.f32 [%0], {%1, %2, %3, %4};"
                 :: "l"(p), "f"(a), "f"(b), "f"(c), "f"(d) : "memory");
}

// sense-reversal grid barrier; safe across graph replays (self-resetting).
__device__ __forceinline__ void grid_barrier(int id) {
    __syncthreads();
    if (threadIdx.x == 0) {
        volatile unsigned* flag = (volatile unsigned*)&g_bar_flag[id];
        __threadfence();
        unsigned v0 = *flag;                    // read before arriving
        unsigned old = atomicAdd(&g_bar_cnt[id], 1u);
        if (old == (unsigned)kBlocks - 1u) {
            g_bar_cnt[id] = 0;                  // all arrived; nobody reads cnt now
            __threadfence();
            *flag = v0 + 1u;                    // release
        } else {
            while (*flag == v0) { }
        }
        __threadfence();
    }
    __syncthreads();
}

// dual inclusive suffix scan over a 256-thread block
__device__ __forceinline__ void dual_block_suffix_scan(float v1, float v2,
                                                       float& o1, float& o2) {
    __shared__ float s1[8], s2[8];
    int tid  = threadIdx.x;
    int lane = tid & 31;
    int w    = tid >> 5;
    float x1 = v1, x2 = v2;
#pragma unroll
    for (int o = 1; o < 32; o <<= 1) {
        float t1 = __shfl_down_sync(0xffffffffu, x1, o);
        float t2 = __shfl_down_sync(0xffffffffu, x2, o);
        if (lane + o < 32) { x1 += t1; x2 += t2; }
    }
    if (lane == 0) { s1[w] = x1; s2[w] = x2; }
    __syncthreads();
    float a1 = 0.f, a2 = 0.f;
#pragma unroll
    for (int j = 0; j < 8; ++j) {
        if (j > w) { a1 += s1[j]; a2 += s2[j]; }
    }
    o1 = x1 + a1;
    o2 = x2 + a2;
    __syncthreads();   // protect smem reuse across calls/phases
}

__global__ void __launch_bounds__(kThreads, 4)
fused_kernel(const float* __restrict__ pos,
             const float* __restrict__ pin_pos,
             const float* __restrict__ nsx,
             const float* __restrict__ nsy,
             const int* __restrict__ netpin_start,
             const int* __restrict__ flat_netpin,
             float* __restrict__ out) {
    int gtid  = blockIdx.x * kThreads + threadIdx.x;
    int lane8 = threadIdx.x & 7;

    // ---------------- phase 1: net bbox + corner scatter ----------------
#pragma unroll 1
    for (int k = 0; k < kNetPasses; ++k) {
        int n = (gtid >> 3) + k * kNetsPerPass;
        bool act = (n < kNumNets);
        float xmin = 1e30f, xmax = -1e30f, ymin = 1e30f, ymax = -1e30f;
        if (act) {
            int s = netpin_start[n];
            int e = netpin_start[n + 1];
            for (int p = s + lane8; p < e; p += 8) {
                int q    = __ldg(&flat_netpin[p]);
                float px = __ldg(&pin_pos[q]);
                float py = __ldg(&pin_pos[kNumPins + q]);
                xmin = fminf(xmin, px); xmax = fmaxf(xmax, px);
                ymin = fminf(ymin, py); ymax = fmaxf(ymax, py);
            }
        }
        // width-8 subwarp reduction (all lanes end with full bbox)
#pragma unroll
        for (int o = 4; o >= 1; o >>= 1) {
            xmin = fminf(xmin, __shfl_xor_sync(0xffffffffu, xmin, o, 8));
            xmax = fmaxf(xmax, __shfl_xor_sync(0xffffffffu, xmax, o, 8));
            ymin = fminf(ymin, __shfl_xor_sync(0xffffffffu, ymin, o, 8));
            ymax = fmaxf(ymax, __shfl_xor_sync(0xffffffffu, ymax, o, 8));
        }
        if (!act) continue;
        float span_x = xmax - xmin;
        float span_y = ymax - ymin;
        float ch = (span_y > kEps) ? (1.0f / fmaxf(span_y, kEps)) : 0.0f;
        float cv = (span_x > kEps) ? (1.0f / fmaxf(span_x, kEps)) : 0.0f;

        // lane l handles one (map, i, j): map=l>>2, i=(l>>1)&1, j=l&1
        int mp = lane8 >> 2;
        int ii = (lane8 >> 1) & 1;
        int jj = lane8 & 1;
        float coef = mp ? cv : ch;
        if (coef != 0.0f) {
            float va = ii ? xmax : xmin;
            float vb = jj ? ymax : ymin;
            int ka = min(max(__float2int_rd(va * kInvBsx), 0), kNbx - 1);
            int kb = min(max(__float2int_rd(vb * kInvBsy), 0), kNby - 1);
            float fa = fminf(fmaxf(va - (float)ka * kBsx, 0.0f), kBsx);
            float fb = fminf(fmaxf(vb - (float)kb * kBsy, 0.0f), kBsy);
            float w  = (ii == jj) ? coef : -coef;
            red4(&g_scat4[mp * kMap + ka * kNby + kb],
                 w * (kBsx * kBsy), w * kBsx * fb, w * fa * kBsy, w * fa * fb);
        }
    }

    grid_barrier(0);

    // ---------------- phase 2: suffix scan along y (blocks 0..511) ----------
    if (blockIdx.x < 512) {
        int m = blockIdx.x >> 8;
        int x = blockIdx.x & 255;
        int y = threadIdx.x;
        int ci = m * kMap + x * kNby + y;
        float4 c = g_scat4[ci];
        g_scat4[ci] = make_float4(0.f, 0.f, 0.f, 0.f);   // re-zero for next run
        float sA, sBy;
        dual_block_suffix_scan(c.x, c.z, sA, sBy);        // inclusive
        float U1 = (sA  - c.x) + c.y;                     // exclusive + Bx'
        float U2 = (sBy - c.z) + c.w;                     // exclusive + P
        int ti = y * kNbx + x;                            // transpose to y-major
        g_T[m * 2 * kMap + ti]        = U1;
        g_T[m * 2 * kMap + kMap + ti] = U2;
    }

    grid_barrier(1);

    // ---------------- phase 3: suffix scan along x + util (blocks 0..255) ---
    if (blockIdx.x < 256) {
        int y = blockIdx.x;
        int x = threadIdx.x;
        int idx = y * kNbx + x;
        float u1h = g_T[idx];
        float u2h = g_T[kMap + idx];
        float u1v = g_T[2 * kMap + idx];
        float u2v = g_T[3 * kMap + idx];
        float sH, sV;
        dual_block_suffix_scan(u1h, u1v, sH, sV);         // inclusive
        float H = (sH - u1h) + u2h;                       // exclusive + U2
        float V = (sV - u1v) + u2v;
        float u = fmaxf(H * kHNorm, V * kVNorm);
        u = fminf(fmaxf(u, 0.5f), 2.0f);
        g_util[idx] = u;
    }

    grid_barrier(2);

    // ---------------- phase 4: per-node gather (2 threads per node) ---------
#pragma unroll 1
    for (int k = 0; k < kNodePasses; ++k) {
        int item = gtid + k * kTotThreads;
        bool act = (item < kNodeItems);
        int node = item >> 1;
        int half = item & 1;
        float acc = 0.0f;
        if (act) {
            float xl = pos[node];
            float yl = pos[kNumNodes + node];
            float xh = xl + nsx[node];
            float yh = yl + nsy[node];
            int bx0 = min(max(__float2int_rd(xl * kInvBsx), 0), kNbx - 1);
            int bx1 = min(max(__float2int_rd(xh * kInvBsx), 0), kNbx - 1);
            int by0 = min(max(__float2int_rd(yl * kInvBsy), 0), kNby - 1);
            int by1 = min(max(__float2int_rd(yh * kInvBsy), 0), kNby - 1);
            float ox[4];
#pragma unroll
            for (int i = 0; i < 4; ++i) {
                float ex = (float)(bx0 + i) * kBsx;
                float o  = fminf(xh, ex + kBsx) - fmaxf(xl, ex);
                ox[i] = fmaxf(o, 0.0f);
            }
            for (int yb = by0 + half; yb <= by1; yb += 2) {
                float ey = (float)yb * kBsy;
                float oy = fminf(yh, ey + kBsy) - fmaxf(yl, ey);
                oy = fmaxf(oy, 0.0f);
                const float* urow = g_util + yb * kNbx;
                float rsum = 0.0f;
#pragma unroll
                for (int i = 0; i < 4; ++i) {
                    int x = bx0 + i;
                    if (x <= bx1) rsum += ox[i] * __ldg(&urow[x]);
                }
                acc += oy * rsum;
            }
        }
        float other = __shfl_xor_sync(0xffffffffu, acc, 1);
        if (act && half == 0) out[node] = acc + other;
    }
}

// ---------------- launcher ----------------
extern "C" void kernel_launch(void* const* d_in, const int* in_sizes, int n_in,
                              void* d_out, int out_size) {
    const float* pos          = (const float*)d_in[0];
    const float* pin_pos      = (const float*)d_in[1];
    const float* node_size_x  = (const float*)d_in[2];
    const float* node_size_y  = (const float*)d_in[3];
    const int*   netpin_start = (const int*)d_in[4];
    const int*   flat_netpin  = (const int*)d_in[5];
    float*       out          = (float*)d_out;

    fused_kernel<<<kBlocks, kThreads>>>(pos, pin_pos, node_size_x, node_size_y,
                                        netpin_start, flat_netpin, out);
}

// round 7
// speedup vs baseline: 1.2381x; 1.2381x over previous
#include <cuda_runtime.h>

// ---------------- problem constants ----------------
constexpr int   kNumNodes   = 120000;
constexpr int   kNumMovable = 100000;
constexpr int   kNumNets    = 100000;
constexpr int   kNumPins    = 400000;
constexpr int   kNbx = 256, kNby = 256;
constexpr int   kMap = kNbx * kNby;
constexpr float kBsx = 1000.0f / 256.0f;      // 3.90625 (exact in fp32)
constexpr float kBsy = 1000.0f / 256.0f;
constexpr float kInvBsx = 256.0f / 1000.0f;
constexpr float kInvBsy = 256.0f / 1000.0f;
constexpr float kEps = 1e-6f;
constexpr float kBinArea = kBsx * kBsy;
constexpr float kHNorm = 1.0f / (kBinArea * 1.5f);   // UNIT_H_CAP
constexpr float kVNorm = 1.0f / (kBinArea * 1.5f);   // UNIT_V_CAP

// ---------------- device scratch (no allocs allowed) ----------------
// g_scat4[m*kMap + x*256 + y] = {A', Bx', By', P}; one red.v4 per corner.
// Zero-initialized at load; scan_y re-zeros it in place each run.
__device__ float4 g_scat4[2 * kMap];
// g_T: [U1h, U2h, U1v, U2v], each y-major [y*256+x]
__device__ float g_T[4 * kMap];
// util, y-major
__device__ float g_util[kMap];

__device__ __forceinline__ void red4(float4* p, float a, float b, float c, float d) {
    asm volatile("red.global.add.v4.f32 [%0], {%1, %2, %3, %4};"
                 :: "l"(p), "f"(a), "f"(b), "f"(c), "f"(d) : "memory");
}

// 8 lanes per net: parallel pin reduction, then EACH lane fires exactly one
// red.v4 for its (map, corner) slot -> scatter chain depth 1.
__global__ void net_kernel(const float* __restrict__ pin_pos,
                           const int* __restrict__ netpin_start,
                           const int* __restrict__ flat_netpin) {
    int t = blockIdx.x * blockDim.x + threadIdx.x;
    int n = t >> 3;               // net id
    int lane8 = threadIdx.x & 7;
    if (n >= kNumNets) return;    // aligned: whole 8-group exits together
    int s = netpin_start[n];
    int e = netpin_start[n + 1];

    float xmin = 1e30f, xmax = -1e30f, ymin = 1e30f, ymax = -1e30f;
    for (int p = s + lane8; p < e; p += 8) {
        int q    = __ldg(&flat_netpin[p]);
        float px = __ldg(&pin_pos[q]);
        float py = __ldg(&pin_pos[kNumPins + q]);
        xmin = fminf(xmin, px); xmax = fmaxf(xmax, px);
        ymin = fminf(ymin, py); ymax = fmaxf(ymax, py);
    }
    // width-8 subwarp reduction; all 8 lanes end with the full bbox
#pragma unroll
    for (int o = 4; o >= 1; o >>= 1) {
        xmin = fminf(xmin, __shfl_xor_sync(0xffffffffu, xmin, o, 8));
        xmax = fmaxf(xmax, __shfl_xor_sync(0xffffffffu, xmax, o, 8));
        ymin = fminf(ymin, __shfl_xor_sync(0xffffffffu, ymin, o, 8));
        ymax = fmaxf(ymax, __shfl_xor_sync(0xffffffffu, ymax, o, 8));
    }
    if (e <= s) return;           // empty net -> no contribution

    float span_x = xmax - xmin;
    float span_y = ymax - ymin;
    float ch = (span_y > kEps) ? (1.0f / fmaxf(span_y, kEps)) : 0.0f;
    float cv = (span_x > kEps) ? (1.0f / fmaxf(span_x, kEps)) : 0.0f;

    // lane l -> (map = l>>2, i = (l>>1)&1, j = l&1)
    int mp = lane8 >> 2;
    int ii = (lane8 >> 1) & 1;
    int jj = lane8 & 1;
    float coef = mp ? cv : ch;
    if (coef == 0.0f) return;
    float va = ii ? xmax : xmin;
    float vb = jj ? ymax : ymin;
    int ka = min(max(__float2int_rd(va * kInvBsx), 0), kNbx - 1);
    int kb = min(max(__float2int_rd(vb * kInvBsy), 0), kNby - 1);
    float fa = fminf(fmaxf(va - (float)ka * kBsx, 0.0f), kBsx);
    float fb = fminf(fmaxf(vb - (float)kb * kBsy, 0.0f), kBsy);
    float w  = (ii == jj) ? coef : -coef;
    red4(&g_scat4[mp * kMap + ka * kNby + kb],
         w * (kBsx * kBsy), w * kBsx * fb, w * fa * kBsy, w * fa * fb);
}

// Dual inclusive suffix scan over a 256-thread block.
__device__ __forceinline__ void dual_block_suffix_scan(float v1, float v2,
                                                       float& o1, float& o2) {
    __shared__ float s1[8], s2[8];
    int tid  = threadIdx.x;
    int lane = tid & 31;
    int w    = tid >> 5;
    float x1 = v1, x2 = v2;
#pragma unroll
    for (int o = 1; o < 32; o <<= 1) {
        float t1 = __shfl_down_sync(0xffffffffu, x1, o);
        float t2 = __shfl_down_sync(0xffffffffu, x2, o);
        if (lane + o < 32) { x1 += t1; x2 += t2; }
    }
    if (lane == 0) { s1[w] = x1; s2[w] = x2; }   // warp suffix totals
    __syncthreads();
    float a1 = 0.f, a2 = 0.f;
#pragma unroll
    for (int j = 0; j < 8; ++j) {
        if (j > w) { a1 += s1[j]; a2 += s2[j]; }
    }
    o1 = x1 + a1;
    o2 = x2 + a2;
}

// Per (m, x) row: U1 = SyExcl(A') + Bx',  U2 = SyExcl(By') + P.
// Coalesced float4 read, in-place re-zero, transposed y-major store.
__global__ void scan_y_kernel() {
    int b = blockIdx.x;           // 0..511
    int m = b >> 8;
    int x = b & 255;
    int y = threadIdx.x;
    int ci = m * kMap + x * kNby + y;
    float4 c = g_scat4[ci];
    g_scat4[ci] = make_float4(0.f, 0.f, 0.f, 0.f);
    float sA, sBy;
    dual_block_suffix_scan(c.x, c.z, sA, sBy);     // inclusive
    float U1 = (sA  - c.x) + c.y;                  // exclusive + Bx'
    float U2 = (sBy - c.z) + c.w;                  // exclusive + P
    float* T1 = g_T + m * 2 * kMap;                // y-major
    float* T2 = T1 + kMap;
    int ti = y * kNbx + x;
    T1[ti] = U1;
    T2[ti] = U2;
}

// Per y column: H = SxExcl(U1h) + U2h, V likewise; fused util map.
__global__ void scan_x_util_kernel() {
    int y = blockIdx.x;
    int x = threadIdx.x;
    int idx = y * kNbx + x;
    float u1h = g_T[idx];
    float u2h = g_T[kMap + idx];
    float u1v = g_T[2 * kMap + idx];
    float u2v = g_T[3 * kMap + idx];
    float sH, sV;
    dual_block_suffix_scan(u1h, u1v, sH, sV);      // inclusive
    float H = (sH - u1h) + u2h;                    // exclusive + U2
    float V = (sV - u1v) + u2v;
    float u = fmaxf(H * kHNorm, V * kVNorm);
    u = fminf(fmaxf(u, 0.5f), 2.0f);
    g_util[idx] = u;      // y-major
}

// 2 threads per node: split y-rows odd/even, pair-combine with shfl.
__global__ void node_kernel(const float* __restrict__ pos,
                            const float* __restrict__ nsx,
                            const float* __restrict__ nsy,
                            float* __restrict__ out) {
    int item = blockIdx.x * blockDim.x + threadIdx.x;
    int m    = item >> 1;
    int half = item & 1;
    if (m >= kNumMovable) return;
    float xl = pos[m];
    float yl = pos[kNumNodes + m];
    float xh = xl + nsx[m];
    float yh = yl + nsy[m];
    int bx0 = min(max(__float2int_rd(xl * kInvBsx), 0), kNbx - 1);
    int bx1 = min(max(__float2int_rd(xh * kInvBsx), 0), kNbx - 1);
    int by0 = min(max(__float2int_rd(yl * kInvBsy), 0), kNby - 1);
    int by1 = min(max(__float2int_rd(yh * kInvBsy), 0), kNby - 1);

    // node width < 8 units -> at most 4 x-bins
    float ox[4];
#pragma unroll
    for (int i = 0; i < 4; ++i) {
        float ex = (float)(bx0 + i) * kBsx;
        float o  = fminf(xh, ex + kBsx) - fmaxf(xl, ex);
        ox[i] = fmaxf(o, 0.0f);
    }

    float acc = 0.0f;
    for (int yb = by0 + half; yb <= by1; yb += 2) {
        float ey = (float)yb * kBsy;
        float oy = fminf(yh, ey + kBsy) - fmaxf(yl, ey);
        oy = fmaxf(oy, 0.0f);
        const float* urow = g_util + yb * kNbx;   // y-major util
        float rsum = 0.0f;
#pragma unroll
        for (int i = 0; i < 4; ++i) {
            int x = bx0 + i;
            if (x <= bx1) rsum += ox[i] * __ldg(&urow[x]);
        }
        acc += oy * rsum;
    }
    acc += __shfl_xor_sync(0xffffffffu, acc, 1);
    if (half == 0) out[m] = acc;
}

// ---------------- launcher ----------------
extern "C" void kernel_launch(void* const* d_in, const int* in_sizes, int n_in,
                              void* d_out, int out_size) {
    const float* pos          = (const float*)d_in[0];
    const float* pin_pos      = (const float*)d_in[1];
    const float* node_size_x  = (const float*)d_in[2];
    const float* node_size_y  = (const float*)d_in[3];
    const int*   netpin_start = (const int*)d_in[4];
    const int*   flat_netpin  = (const int*)d_in[5];
    float*       out          = (float*)d_out;

    net_kernel<<<(kNumNets * 8 + 255) / 256, 256>>>(pin_pos, netpin_start, flat_netpin);
    scan_y_kernel<<<512, 256>>>();
    scan_x_util_kernel<<<256, 256>>>();
    node_kernel<<<(kNumMovable * 2 + 255) / 256, 256>>>(pos, node_size_x, node_size_y, out);
}

// round 8
// speedup vs baseline: 1.2702x; 1.0260x over previous
#include <cuda_runtime.h>

// ---------------- problem constants ----------------
constexpr int   kNumNodes   = 120000;
constexpr int   kNumMovable = 100000;
constexpr int   kNumNets    = 100000;
constexpr int   kNumPins    = 400000;
constexpr int   kNbx = 256, kNby = 256;
constexpr int   kMap = kNbx * kNby;
constexpr float kBsx = 1000.0f / 256.0f;      // 3.90625 (exact in fp32)
constexpr float kBsy = 1000.0f / 256.0f;
constexpr float kInvBsx = 256.0f / 1000.0f;
constexpr float kInvBsy = 256.0f / 1000.0f;
constexpr float kEps = 1e-6f;
constexpr float kBinArea = kBsx * kBsy;
constexpr float kHNorm = 1.0f / (kBinArea * 1.5f);   // UNIT_H_CAP
constexpr float kVNorm = 1.0f / (kBinArea * 1.5f);   // UNIT_V_CAP

// ---------------- device scratch (no allocs allowed) ----------------
// g_scat4[m*kMap + x*256 + y] = {A', Bx', By', P}; one red.v4 per corner.
// Zero-initialized at load; scan_y re-zeros it in place each run.
__device__ float4 g_scat4[2 * kMap];
// g_T: [U1h, U2h, U1v, U2v], each y-major [y*256+x]
__device__ float g_T[4 * kMap];
// util, y-major
__device__ float g_util[kMap];

__device__ __forceinline__ void red4(float4* p, float a, float b, float c, float d) {
    asm volatile("red.global.add.v4.f32 [%0], {%1, %2, %3, %4};"
                 :: "l"(p), "f"(a), "f"(b), "f"(c), "f"(d) : "memory");
}

// 8 lanes per net: parallel pin reduction, then EACH lane fires exactly one
// red.v4 for its (map, corner) slot -> scatter chain depth 1.
__global__ void net_kernel(const float* __restrict__ pin_pos,
                           const int* __restrict__ netpin_start,
                           const int* __restrict__ flat_netpin) {
    int t = blockIdx.x * blockDim.x + threadIdx.x;
    int n = t >> 3;               // net id
    int lane8 = threadIdx.x & 7;
    if (n >= kNumNets) return;    // aligned: whole 8-group exits together
    int s = netpin_start[n];
    int e = netpin_start[n + 1];

    float xmin = 1e30f, xmax = -1e30f, ymin = 1e30f, ymax = -1e30f;
    for (int p = s + lane8; p < e; p += 8) {
        int q    = __ldg(&flat_netpin[p]);
        float px = __ldg(&pin_pos[q]);
        float py = __ldg(&pin_pos[kNumPins + q]);
        xmin = fminf(xmin, px); xmax = fmaxf(xmax, px);
        ymin = fminf(ymin, py); ymax = fmaxf(ymax, py);
    }
    // width-8 subwarp reduction; all 8 lanes end with the full bbox
#pragma unroll
    for (int o = 4; o >= 1; o >>= 1) {
        xmin = fminf(xmin, __shfl_xor_sync(0xffffffffu, xmin, o, 8));
        xmax = fmaxf(xmax, __shfl_xor_sync(0xffffffffu, xmax, o, 8));
        ymin = fminf(ymin, __shfl_xor_sync(0xffffffffu, ymin, o, 8));
        ymax = fmaxf(ymax, __shfl_xor_sync(0xffffffffu, ymax, o, 8));
    }
    if (e <= s) return;           // empty net -> no contribution

    float span_x = xmax - xmin;
    float span_y = ymax - ymin;
    float ch = (span_y > kEps) ? (1.0f / fmaxf(span_y, kEps)) : 0.0f;
    float cv = (span_x > kEps) ? (1.0f / fmaxf(span_x, kEps)) : 0.0f;

    // lane l -> (map = l>>2, i = (l>>1)&1, j = l&1)
    int mp = lane8 >> 2;
    int ii = (lane8 >> 1) & 1;
    int jj = lane8 & 1;
    float coef = mp ? cv : ch;
    if (coef == 0.0f) return;
    float va = ii ? xmax : xmin;
    float vb = jj ? ymax : ymin;
    int ka = min(max(__float2int_rd(va * kInvBsx), 0), kNbx - 1);
    int kb = min(max(__float2int_rd(vb * kInvBsy), 0), kNby - 1);
    float fa = fminf(fmaxf(va - (float)ka * kBsx, 0.0f), kBsx);
    float fb = fminf(fmaxf(vb - (float)kb * kBsy, 0.0f), kBsy);
    float w  = (ii == jj) ? coef : -coef;
    red4(&g_scat4[mp * kMap + ka * kNby + kb],
         w * (kBsx * kBsy), w * kBsx * fb, w * fa * kBsy, w * fa * fb);
}

// Dual inclusive suffix scan over a 256-thread block.
__device__ __forceinline__ void dual_block_suffix_scan(float v1, float v2,
                                                       float& o1, float& o2) {
    __shared__ float s1[8], s2[8];
    int tid  = threadIdx.x;
    int lane = tid & 31;
    int w    = tid >> 5;
    float x1 = v1, x2 = v2;
#pragma unroll
    for (int o = 1; o < 32; o <<= 1) {
        float t1 = __shfl_down_sync(0xffffffffu, x1, o);
        float t2 = __shfl_down_sync(0xffffffffu, x2, o);
        if (lane + o < 32) { x1 += t1; x2 += t2; }
    }
    if (lane == 0) { s1[w] = x1; s2[w] = x2; }   // warp suffix totals
    __syncthreads();
    float a1 = 0.f, a2 = 0.f;
#pragma unroll
    for (int j = 0; j < 8; ++j) {
        if (j > w) { a1 += s1[j]; a2 += s2[j]; }
    }
    o1 = x1 + a1;
    o2 = x2 + a2;
}

// Per (m, x) row: U1 = SyExcl(A') + Bx',  U2 = SyExcl(By') + P.
// Coalesced float4 read, in-place re-zero, transposed y-major store.
__global__ void scan_y_kernel() {
    int b = blockIdx.x;           // 0..511
    int m = b >> 8;
    int x = b & 255;
    int y = threadIdx.x;
    int ci = m * kMap + x * kNby + y;
    float4 c = g_scat4[ci];
    g_scat4[ci] = make_float4(0.f, 0.f, 0.f, 0.f);
    float sA, sBy;
    dual_block_suffix_scan(c.x, c.z, sA, sBy);     // inclusive
    float U1 = (sA  - c.x) + c.y;                  // exclusive + Bx'
    float U2 = (sBy - c.z) + c.w;                  // exclusive + P
    float* T1 = g_T + m * 2 * kMap;                // y-major
    float* T2 = T1 + kMap;
    int ti = y * kNbx + x;
    T1[ti] = U1;
    T2[ti] = U2;
}

// Per y column: H = SxExcl(U1h) + U2h, V likewise; fused util map.
__global__ void scan_x_util_kernel() {
    int y = blockIdx.x;
    int x = threadIdx.x;
    int idx = y * kNbx + x;
    float u1h = g_T[idx];
    float u2h = g_T[kMap + idx];
    float u1v = g_T[2 * kMap + idx];
    float u2v = g_T[3 * kMap + idx];
    float sH, sV;
    dual_block_suffix_scan(u1h, u1v, sH, sV);      // inclusive
    float H = (sH - u1h) + u2h;                    // exclusive + U2
    float V = (sV - u1v) + u2v;
    float u = fmaxf(H * kHNorm, V * kVNorm);
    u = fminf(fmaxf(u, 0.5f), 2.0f);
    g_util[idx] = u;      // y-major
}

// One thread per node; branch-free fixed 4x3 window.
// Clamp-overlap weights are exactly 0 for bins outside the node extent
// (and the domain guarantees xh<1000, yh<1000, so no phantom weight at the
// top edge). Indices are clamped only to stay in-bounds; all 12 util gathers
// are independent -> single exposed L2 latency.
__global__ void node_kernel(const float* __restrict__ pos,
                            const float* __restrict__ nsx,
                            const float* __restrict__ nsy,
                            float* __restrict__ out) {
    int m = blockIdx.x * blockDim.x + threadIdx.x;
    if (m >= kNumMovable) return;
    float xl = pos[m];
    float yl = pos[kNumNodes + m];
    float xh = xl + nsx[m];
    float yh = yl + nsy[m];
    int bx0 = min(max(__float2int_rd(xl * kInvBsx), 0), kNbx - 1);
    int by0 = min(max(__float2int_rd(yl * kInvBsy), 0), kNby - 1);

    // node_size_x < 8  -> at most 4 x-bins; node_size_y < 4 -> at most 3 y-bins
    float ox[4], oy[3];
#pragma unroll
    for (int i = 0; i < 4; ++i) {
        float ex = (float)(bx0 + i) * kBsx;
        ox[i] = fmaxf(fminf(xh, ex + kBsx) - fmaxf(xl, ex), 0.0f);
    }
#pragma unroll
    for (int j = 0; j < 3; ++j) {
        float ey = (float)(by0 + j) * kBsy;
        oy[j] = fmaxf(fminf(yh, ey + kBsy) - fmaxf(yl, ey), 0.0f);
    }

    // all 12 gathers issued back-to-back (independent)
    float u[3][4];
#pragma unroll
    for (int j = 0; j < 3; ++j) {
        int yb = min(by0 + j, kNby - 1);
        const float* urow = g_util + yb * kNbx;
#pragma unroll
        for (int i = 0; i < 4; ++i) {
            int x = min(bx0 + i, kNbx - 1);
            u[j][i] = __ldg(&urow[x]);
        }
    }

    float acc = 0.0f;
#pragma unroll
    for (int j = 0; j < 3; ++j) {
        float rsum = 0.0f;
#pragma unroll
        for (int i = 0; i < 4; ++i) rsum += ox[i] * u[j][i];
        acc += oy[j] * rsum;
    }
    out[m] = acc;
}

// ---------------- launcher ----------------
extern "C" void kernel_launch(void* const* d_in, const int* in_sizes, int n_in,
                              void* d_out, int out_size) {
    const float* pos          = (const float*)d_in[0];
    const float* pin_pos      = (const float*)d_in[1];
    const float* node_size_x  = (const float*)d_in[2];
    const float* node_size_y  = (const float*)d_in[3];
    const int*   netpin_start = (const int*)d_in[4];
    const int*   flat_netpin  = (const int*)d_in[5];
    float*       out          = (float*)d_out;

    net_kernel<<<(kNumNets * 8 + 255) / 256, 256>>>(pin_pos, netpin_start, flat_netpin);
    scan_y_kernel<<<512, 256>>>();
    scan_x_util_kernel<<<256, 256>>>();
    node_kernel<<<(kNumMovable + 255) / 256, 256>>>(pos, node_size_x, node_size_y, out);
}